// round 4
// baseline (speedup 1.0000x reference)
#include <cuda_runtime.h>

typedef unsigned long long u64;

__device__ __forceinline__ u64 pk2(float lo, float hi) {
    u64 r; asm("mov.b64 %0,{%1,%2};" : "=l"(r) : "f"(lo), "f"(hi)); return r;
}
__device__ __forceinline__ float2 up2(u64 v) {
    float2 f; asm("mov.b64 {%0,%1},%2;" : "=f"(f.x), "=f"(f.y) : "l"(v)); return f;
}
__device__ __forceinline__ u64 fma2(u64 a, u64 b, u64 c) {
    u64 d; asm("fma.rn.f32x2 %0,%1,%2,%3;" : "=l"(d) : "l"(a), "l"(b), "l"(c)); return d;
}
__device__ __forceinline__ u64 add2(u64 a, u64 b) {
    u64 d; asm("add.rn.f32x2 %0,%1,%2;" : "=l"(d) : "l"(a), "l"(b)); return d;
}
__device__ __forceinline__ u64 clamp2(u64 v) {
    float2 f = up2(v);
    f.x = fminf(fmaxf(f.x, -1.0f), 1.0f);
    f.y = fminf(fmaxf(f.y, -1.0f), 1.0f);
    return pk2(f.x, f.y);
}

// constant-memory u64 (duplicated-pair) layout — everything except W1
#define C_W2 0        // 144  (12x12)
#define C_B2 144      // 12
#define C_W3 156      // 48   (12x4)
#define C_B3 204      // 4
#define C_V1 208      // 4640 (145x32)
#define C_C1 4848     // 32
#define C_C2 4880     // 32
#define C_V3 4912     // 32
#define C_C3 4944     // 1
#define C_V2 4945     // 1024 (32x32)
#define C_B1 5969     // 12
#define N_CST 5981    // 47848 bytes

__constant__ u64 cst[N_CST];
__device__   u64 g_stage[N_CST];

__global__ void prep_kernel(
    const float* __restrict__ b1,
    const float* __restrict__ W2, const float* __restrict__ b2,
    const float* __restrict__ W3, const float* __restrict__ b3,
    const float* __restrict__ V1, const float* __restrict__ c1,
    const float* __restrict__ V2, const float* __restrict__ c2,
    const float* __restrict__ V3, const float* __restrict__ c3)
{
    int i = blockIdx.x * blockDim.x + threadIdx.x;
    if (i < 144)  { float v = W2[i]; g_stage[C_W2 + i] = pk2(v, v); }
    if (i < 12)   { float v = b2[i]; g_stage[C_B2 + i] = pk2(v, v);
                    float u = b1[i]; g_stage[C_B1 + i] = pk2(u, u); }
    if (i < 48)   { float v = W3[i]; g_stage[C_W3 + i] = pk2(v, v); }
    if (i < 4)    { float v = b3[i]; g_stage[C_B3 + i] = pk2(v, v); }
    if (i < 4640) { float v = V1[i]; g_stage[C_V1 + i] = pk2(v, v); }
    if (i < 32)   { float v = c1[i]; g_stage[C_C1 + i] = pk2(v, v);
                    float u = c2[i]; g_stage[C_C2 + i] = pk2(u, u);
                    float w = V3[i]; g_stage[C_V3 + i] = pk2(w, w); }
    if (i < 1)    { float v = c3[0]; g_stage[C_C3]     = pk2(v, v); }
    if (i < 1024) { float v = V2[i]; g_stage[C_V2 + i] = pk2(v, v); }
}

__global__ void __launch_bounds__(128, 3) lila_kernel(
    const float* __restrict__ inp,
    const float* __restrict__ W1,
    float* __restrict__ out, int nhalf)
{
    __shared__ u64 sw1[648];   // W1 duplicated pairs only (5184 B)

    for (int i = threadIdx.x; i < 648; i += 128) { float v = W1[i]; sw1[i] = pk2(v, v); }
    __syncthreads();

    int t = blockIdx.x * 128 + threadIdx.x;
    if (t >= nhalf) return;
    const float* p0 = inp + (size_t)(2 * t) * 385;   // even word offset -> 8B aligned
    const float* p1 = p0 + 385;                      // odd word offset  -> NOT 8B aligned

    u64 acc[32];
    #pragma unroll
    for (int j = 0; j < 32; j++) acc[j] = 0ull;

    // window pairs: (x, yy) and (x, yy+1), x in 0..5, yy in {0,2,4}
    #pragma unroll 1
    for (int wp = 0; wp < 18; wp++) {
        int x  = wp / 3;
        int yy = (wp - x * 3) * 2;
        int cbase = x * 48 + yy * 6;

        u64 ha[12], hb[12];
        #pragma unroll
        for (int n = 0; n < 12; n++) { ha[n] = cst[C_B1 + n]; hb[n] = ha[n]; }

        // layer 1: both windows need cols [cbase+ox*48 .. +23].
        // Sample 0: 12 aligned float2 loads. Sample 1 (odd base): 13 float2
        // loads from (r1-1), aligned, carry across phases.
        #pragma unroll 1
        for (int ox = 0; ox < 3; ox++) {
            const float*  r0 = p0 + cbase + ox * 48;
            const float*  r1 = p1 + cbase + ox * 48;
            const float2* q0 = reinterpret_cast<const float2*>(r0);
            const float2* q1 = reinterpret_cast<const float2*>(r1 - 1);
            const u64* wk = sw1 + ox * 216;

            u64 v[12];
            float carry;
            {
                float2 A0=__ldg(q0+0),A1=__ldg(q0+1),A2=__ldg(q0+2),
                       A3=__ldg(q0+3),A4=__ldg(q0+4),A5=__ldg(q0+5);
                float2 B0=__ldg(q1+0),B1=__ldg(q1+1),B2=__ldg(q1+2),B3=__ldg(q1+3),
                       B4=__ldg(q1+4),B5=__ldg(q1+5),B6=__ldg(q1+6);
                v[0]=pk2(A0.x,B0.y);  v[1]=pk2(A0.y,B1.x);
                v[2]=pk2(A1.x,B1.y);  v[3]=pk2(A1.y,B2.x);
                v[4]=pk2(A2.x,B2.y);  v[5]=pk2(A2.y,B3.x);
                v[6]=pk2(A3.x,B3.y);  v[7]=pk2(A3.y,B4.x);
                v[8]=pk2(A4.x,B4.y);  v[9]=pk2(A4.y,B5.x);
                v[10]=pk2(A5.x,B5.y); v[11]=pk2(A5.y,B6.x);
                carry = B6.y;
            }
            #pragma unroll
            for (int kk = 0; kk < 6; kk++) {
                u64 va = v[kk], vb = v[kk + 6];
                #pragma unroll
                for (int n = 0; n < 12; n++) {
                    u64 wv = wk[kk * 12 + n];
                    ha[n] = fma2(va, wv, ha[n]);
                    hb[n] = fma2(vb, wv, hb[n]);
                }
            }
            {
                #pragma unroll
                for (int i = 0; i < 6; i++) v[i] = v[i + 6];
                float2 A6=__ldg(q0+6),A7=__ldg(q0+7),A8=__ldg(q0+8);
                float2 B7=__ldg(q1+7),B8=__ldg(q1+8),B9=__ldg(q1+9);
                v[6] =pk2(A6.x,carry); v[7] =pk2(A6.y,B7.x);
                v[8] =pk2(A7.x,B7.y);  v[9] =pk2(A7.y,B8.x);
                v[10]=pk2(A8.x,B8.y);  v[11]=pk2(A8.y,B9.x);
                carry = B9.y;
            }
            #pragma unroll
            for (int kk = 0; kk < 6; kk++) {
                u64 va = v[kk], vb = v[kk + 6];
                #pragma unroll
                for (int n = 0; n < 12; n++) {
                    u64 wv = wk[(6 + kk) * 12 + n];
                    ha[n] = fma2(va, wv, ha[n]);
                    hb[n] = fma2(vb, wv, hb[n]);
                }
            }
            {
                #pragma unroll
                for (int i = 0; i < 6; i++) v[i] = v[i + 6];
                float2 A9=__ldg(q0+9),A10=__ldg(q0+10),A11=__ldg(q0+11);
                float2 B10=__ldg(q1+10),B11=__ldg(q1+11),B12=__ldg(q1+12);
                v[6] =pk2(A9.x,carry);  v[7] =pk2(A9.y,B10.x);
                v[8] =pk2(A10.x,B10.y); v[9] =pk2(A10.y,B11.x);
                v[10]=pk2(A11.x,B11.y); v[11]=pk2(A11.y,B12.x);
            }
            #pragma unroll
            for (int kk = 0; kk < 6; kk++) {
                u64 va = v[kk], vb = v[kk + 6];
                #pragma unroll
                for (int n = 0; n < 12; n++) {
                    u64 wv = wk[(12 + kk) * 12 + n];
                    ha[n] = fma2(va, wv, ha[n]);
                    hb[n] = fma2(vb, wv, hb[n]);
                }
            }
        }
        #pragma unroll
        for (int n = 0; n < 12; n++) { ha[n] = clamp2(ha[n]); hb[n] = clamp2(hb[n]); }

        // layer 2: 12 -> 12 (weights from constant port)
        u64 ga[12], gb[12];
        #pragma unroll
        for (int n = 0; n < 12; n++) { ga[n] = cst[C_B2 + n]; gb[n] = ga[n]; }
        #pragma unroll 4
        for (int k = 0; k < 12; k++) {
            #pragma unroll
            for (int n = 0; n < 12; n++) {
                u64 wv = cst[C_W2 + k * 12 + n];
                ga[n] = fma2(ha[k], wv, ga[n]);
                gb[n] = fma2(hb[k], wv, gb[n]);
            }
        }
        #pragma unroll
        for (int n = 0; n < 12; n++) { ga[n] = clamp2(ga[n]); gb[n] = clamp2(gb[n]); }

        // layer 3: 12 -> 4
        u64 sa[4], sb[4];
        #pragma unroll
        for (int q = 0; q < 4; q++) { sa[q] = cst[C_B3 + q]; sb[q] = sa[q]; }
        #pragma unroll
        for (int k = 0; k < 12; k++) {
            #pragma unroll
            for (int q = 0; q < 4; q++) {
                u64 wv = cst[C_W3 + k * 4 + q];
                sa[q] = fma2(ga[k], wv, sa[q]);
                sb[q] = fma2(gb[k], wv, sb[q]);
            }
        }
        #pragma unroll
        for (int q = 0; q < 4; q++) { sa[q] = clamp2(sa[q]); sb[q] = clamp2(sb[q]); }

        // fold sight into the V1 accumulator: rows (wa*4+q), (wb*4+q)
        const int v1base = C_V1 + (x * 6 + yy) * 4 * 32;
        #pragma unroll
        for (int q = 0; q < 4; q++) {
            #pragma unroll
            for (int j = 0; j < 32; j++) {
                acc[j] = fma2(sa[q], cst[v1base + q * 32 + j],       acc[j]);
                acc[j] = fma2(sb[q], cst[v1base + (4 + q) * 32 + j], acc[j]);
            }
        }
    }

    // vision[144] = inp[:,384]; finish V1, add c1, clamp -> e1
    u64 last = pk2(__ldg(p0 + 384), __ldg(p1 + 384));
    u64 e1[32];
    #pragma unroll
    for (int j = 0; j < 32; j++) {
        u64 v = fma2(last, cst[C_V1 + 144 * 32 + j], acc[j]);
        e1[j] = clamp2(add2(v, cst[C_C1 + j]));
    }

    // V2 (32->32) + V3 (32->1) fused
    u64 o = cst[C_C3];
    #pragma unroll 1
    for (int j = 0; j < 32; j++) {
        u64 e = cst[C_C2 + j];
        #pragma unroll
        for (int k = 0; k < 32; k++) {
            e = fma2(e1[k], cst[C_V2 + k * 32 + j], e);
        }
        e = clamp2(e);
        o = fma2(e, cst[C_V3 + j], o);
    }
    o = clamp2(o);

    reinterpret_cast<float2*>(out)[t] = up2(o);
}

extern "C" void kernel_launch(void* const* d_in, const int* in_sizes, int n_in,
                              void* d_out, int out_size) {
    const float* inp = (const float*)d_in[0];
    const float* W1  = (const float*)d_in[1];
    const float* b1  = (const float*)d_in[2];
    const float* W2  = (const float*)d_in[3];
    const float* b2  = (const float*)d_in[4];
    const float* W3  = (const float*)d_in[5];
    const float* b3  = (const float*)d_in[6];
    const float* V1  = (const float*)d_in[7];
    const float* c1  = (const float*)d_in[8];
    const float* V2  = (const float*)d_in[9];
    const float* c2  = (const float*)d_in[10];
    const float* V3  = (const float*)d_in[11];
    const float* c3  = (const float*)d_in[12];

    // 1) pack duplicated-pair weights into the staging buffer
    prep_kernel<<<10, 512>>>(b1, W2, b2, W3, b3, V1, c1, V2, c2, V3, c3);

    // 2) stage -> constant bank (D2D async memcpy, graph-capturable)
    void* stage_ptr = nullptr;
    cudaGetSymbolAddress(&stage_ptr, g_stage);
    cudaMemcpyToSymbolAsync(cst, stage_ptr, N_CST * sizeof(u64), 0,
                            cudaMemcpyDeviceToDevice, 0);

    // 3) main kernel
    int B = in_sizes[0] / 385;
    int nhalf = B / 2;
    int blocks = (nhalf + 127) / 128;
    lila_kernel<<<blocks, 128>>>(inp, W1, (float*)d_out, nhalf);
}

// round 6
// speedup vs baseline: 1.0710x; 1.0710x over previous
#include <cuda_runtime.h>

typedef unsigned long long u64;

__device__ __forceinline__ u64 pk2(float lo, float hi) {
    u64 r; asm("mov.b64 %0,{%1,%2};" : "=l"(r) : "f"(lo), "f"(hi)); return r;
}
__device__ __forceinline__ float2 up2(u64 v) {
    float2 f; asm("mov.b64 {%0,%1},%2;" : "=f"(f.x), "=f"(f.y) : "l"(v)); return f;
}
__device__ __forceinline__ u64 fma2(u64 a, u64 b, u64 c) {
    u64 d; asm("fma.rn.f32x2 %0,%1,%2,%3;" : "=l"(d) : "l"(a), "l"(b), "l"(c)); return d;
}
__device__ __forceinline__ u64 add2(u64 a, u64 b) {
    u64 d; asm("add.rn.f32x2 %0,%1,%2;" : "=l"(d) : "l"(a), "l"(b)); return d;
}
__device__ __forceinline__ u64 clamp2(u64 v) {
    float2 f = up2(v);
    f.x = fminf(fmaxf(f.x, -1.0f), 1.0f);
    f.y = fminf(fmaxf(f.y, -1.0f), 1.0f);
    return pk2(f.x, f.y);
}

// constant bank: V-side weights + small layers (duplicated {w,w} pairs)
#define C_W3 0        // 48   (12x4)
#define C_B3 48       // 4
#define C_V1 52       // 4640 (145x32)
#define C_C1 4692     // 32
#define C_C2 4724     // 32
#define C_V3 4756     // 32
#define C_C3 4788     // 1
#define C_V2 4789     // 1024 (32x32)
#define C_B1 5813     // 12
#define C_B2 5825     // 12
#define N_CST 5837    // 46696 bytes

__constant__ u64 cst[N_CST];
__device__   u64 g_stage[N_CST];

__global__ void prep_kernel(
    const float* __restrict__ b1, const float* __restrict__ b2,
    const float* __restrict__ W3, const float* __restrict__ b3,
    const float* __restrict__ V1, const float* __restrict__ c1,
    const float* __restrict__ V2, const float* __restrict__ c2,
    const float* __restrict__ V3, const float* __restrict__ c3)
{
    int i = blockIdx.x * blockDim.x + threadIdx.x;
    if (i < 12)   { float v = b1[i]; g_stage[C_B1 + i] = pk2(v, v);
                    float u = b2[i]; g_stage[C_B2 + i] = pk2(u, u); }
    if (i < 48)   { float v = W3[i]; g_stage[C_W3 + i] = pk2(v, v); }
    if (i < 4)    { float v = b3[i]; g_stage[C_B3 + i] = pk2(v, v); }
    if (i < 4640) { float v = V1[i]; g_stage[C_V1 + i] = pk2(v, v); }
    if (i < 32)   { float v = c1[i]; g_stage[C_C1 + i] = pk2(v, v);
                    float u = c2[i]; g_stage[C_C2 + i] = pk2(u, u);
                    float w = V3[i]; g_stage[C_V3 + i] = pk2(w, w); }
    if (i < 1)    { float v = c3[0]; g_stage[C_C3]     = pk2(v, v); }
    if (i < 1024) { float v = V2[i]; g_stage[C_V2 + i] = pk2(v, v); }
}

__global__ void __launch_bounds__(128, 3) lila_kernel(
    const float* __restrict__ inp,
    const float* __restrict__ W1, const float* __restrict__ W2,
    float* __restrict__ out, int nhalf)
{
    __shared__ u64 sw1[648];   // W1 pairs (5184 B)
    __shared__ u64 sw2[144];   // W2 pairs (1152 B)

    for (int i = threadIdx.x; i < 648; i += 128) { float v = W1[i]; sw1[i] = pk2(v, v); }
    for (int i = threadIdx.x; i < 144; i += 128) { float v = W2[i]; sw2[i] = pk2(v, v); }
    __syncthreads();

    int t = blockIdx.x * 128 + threadIdx.x;
    if (t >= nhalf) return;
    const float* p0 = inp + (size_t)(2 * t) * 385;   // 8B aligned
    const float* p1 = p0 + 385;                      // odd word offset

    u64 acc[32];
    #pragma unroll
    for (int j = 0; j < 32; j++) acc[j] = 0ull;

    // window pairs: (x, yy) and (x, yy+1), x in 0..5, yy in {0,2,4}
    #pragma unroll 1
    for (int wp = 0; wp < 18; wp++) {
        int x  = wp / 3;
        int yy = (wp - x * 3) * 2;
        int cbase = x * 48 + yy * 6;

        u64 ha[12], hb[12];
        #pragma unroll
        for (int n = 0; n < 12; n++) { ha[n] = cst[C_B1 + n]; hb[n] = ha[n]; }

        #pragma unroll 1
        for (int ox = 0; ox < 3; ox++) {
            const float*  r0 = p0 + cbase + ox * 48;
            const float*  r1 = p1 + cbase + ox * 48;
            const float2* q0 = reinterpret_cast<const float2*>(r0);
            const float2* q1 = reinterpret_cast<const float2*>(r1 - 1);
            const u64* wk = sw1 + ox * 216;

            u64 v[12];
            float carry;
            {
                float2 A0=__ldg(q0+0),A1=__ldg(q0+1),A2=__ldg(q0+2),
                       A3=__ldg(q0+3),A4=__ldg(q0+4),A5=__ldg(q0+5);
                float2 B0=__ldg(q1+0),B1=__ldg(q1+1),B2=__ldg(q1+2),B3=__ldg(q1+3),
                       B4=__ldg(q1+4),B5=__ldg(q1+5),B6=__ldg(q1+6);
                v[0]=pk2(A0.x,B0.y);  v[1]=pk2(A0.y,B1.x);
                v[2]=pk2(A1.x,B1.y);  v[3]=pk2(A1.y,B2.x);
                v[4]=pk2(A2.x,B2.y);  v[5]=pk2(A2.y,B3.x);
                v[6]=pk2(A3.x,B3.y);  v[7]=pk2(A3.y,B4.x);
                v[8]=pk2(A4.x,B4.y);  v[9]=pk2(A4.y,B5.x);
                v[10]=pk2(A5.x,B5.y); v[11]=pk2(A5.y,B6.x);
                carry = B6.y;
            }
            #pragma unroll
            for (int kk = 0; kk < 6; kk++) {
                u64 va = v[kk], vb = v[kk + 6];
                #pragma unroll
                for (int n = 0; n < 12; n++) {
                    u64 wv = wk[kk * 12 + n];
                    ha[n] = fma2(va, wv, ha[n]);
                    hb[n] = fma2(vb, wv, hb[n]);
                }
            }
            {
                #pragma unroll
                for (int i = 0; i < 6; i++) v[i] = v[i + 6];
                float2 A6=__ldg(q0+6),A7=__ldg(q0+7),A8=__ldg(q0+8);
                float2 B7=__ldg(q1+7),B8=__ldg(q1+8),B9=__ldg(q1+9);
                v[6] =pk2(A6.x,carry); v[7] =pk2(A6.y,B7.x);
                v[8] =pk2(A7.x,B7.y);  v[9] =pk2(A7.y,B8.x);
                v[10]=pk2(A8.x,B8.y);  v[11]=pk2(A8.y,B9.x);
                carry = B9.y;
            }
            #pragma unroll
            for (int kk = 0; kk < 6; kk++) {
                u64 va = v[kk], vb = v[kk + 6];
                #pragma unroll
                for (int n = 0; n < 12; n++) {
                    u64 wv = wk[(6 + kk) * 12 + n];
                    ha[n] = fma2(va, wv, ha[n]);
                    hb[n] = fma2(vb, wv, hb[n]);
                }
            }
            {
                #pragma unroll
                for (int i = 0; i < 6; i++) v[i] = v[i + 6];
                float2 A9=__ldg(q0+9),A10=__ldg(q0+10),A11=__ldg(q0+11);
                float2 B10=__ldg(q1+10),B11=__ldg(q1+11),B12=__ldg(q1+12);
                v[6] =pk2(A9.x,carry);  v[7] =pk2(A9.y,B10.x);
                v[8] =pk2(A10.x,B10.y); v[9] =pk2(A10.y,B11.x);
                v[10]=pk2(A11.x,B11.y); v[11]=pk2(A11.y,B12.x);
            }
            #pragma unroll
            for (int kk = 0; kk < 6; kk++) {
                u64 va = v[kk], vb = v[kk + 6];
                #pragma unroll
                for (int n = 0; n < 12; n++) {
                    u64 wv = wk[(12 + kk) * 12 + n];
                    ha[n] = fma2(va, wv, ha[n]);
                    hb[n] = fma2(vb, wv, hb[n]);
                }
            }
        }
        #pragma unroll
        for (int n = 0; n < 12; n++) { ha[n] = clamp2(ha[n]); hb[n] = clamp2(hb[n]); }

        // layer 2: 12 -> 12 (smem)
        u64 ga[12], gb[12];
        #pragma unroll
        for (int n = 0; n < 12; n++) { ga[n] = cst[C_B2 + n]; gb[n] = ga[n]; }
        #pragma unroll 4
        for (int k = 0; k < 12; k++) {
            #pragma unroll
            for (int n = 0; n < 12; n++) {
                u64 wv = sw2[k * 12 + n];
                ga[n] = fma2(ha[k], wv, ga[n]);
                gb[n] = fma2(hb[k], wv, gb[n]);
            }
        }
        #pragma unroll
        for (int n = 0; n < 12; n++) { ga[n] = clamp2(ga[n]); gb[n] = clamp2(gb[n]); }

        // layer 3: 12 -> 4 (const port)
        u64 sa[4], sb[4];
        #pragma unroll
        for (int q = 0; q < 4; q++) { sa[q] = cst[C_B3 + q]; sb[q] = sa[q]; }
        #pragma unroll
        for (int k = 0; k < 12; k++) {
            #pragma unroll
            for (int q = 0; q < 4; q++) {
                u64 wv = cst[C_W3 + k * 4 + q];
                sa[q] = fma2(ga[k], wv, sa[q]);
                sb[q] = fma2(gb[k], wv, sb[q]);
            }
        }
        #pragma unroll
        for (int q = 0; q < 4; q++) { sa[q] = clamp2(sa[q]); sb[q] = clamp2(sb[q]); }

        // fold sight into V1 accumulator (const port)
        const int v1base = C_V1 + (x * 6 + yy) * 4 * 32;
        #pragma unroll
        for (int q = 0; q < 4; q++) {
            #pragma unroll
            for (int j = 0; j < 32; j++) {
                acc[j] = fma2(sa[q], cst[v1base + q * 32 + j],       acc[j]);
                acc[j] = fma2(sb[q], cst[v1base + (4 + q) * 32 + j], acc[j]);
            }
        }
    }

    // finish V1 with inp[:,384], add c1, clamp -> e1
    u64 last = pk2(__ldg(p0 + 384), __ldg(p1 + 384));
    u64 e1[32];
    #pragma unroll
    for (int j = 0; j < 32; j++) {
        u64 v = fma2(last, cst[C_V1 + 144 * 32 + j], acc[j]);
        e1[j] = clamp2(add2(v, cst[C_C1 + j]));
    }

    // V2 (32->32) + V3 (32->1) fused (const port)
    u64 o = cst[C_C3];
    #pragma unroll 1
    for (int j = 0; j < 32; j++) {
        u64 e = cst[C_C2 + j];
        #pragma unroll
        for (int k = 0; k < 32; k++) {
            e = fma2(e1[k], cst[C_V2 + k * 32 + j], e);
        }
        e = clamp2(e);
        o = fma2(e, cst[C_V3 + j], o);
    }
    o = clamp2(o);

    reinterpret_cast<float2*>(out)[t] = up2(o);
}

extern "C" void kernel_launch(void* const* d_in, const int* in_sizes, int n_in,
                              void* d_out, int out_size) {
    const float* inp = (const float*)d_in[0];
    const float* W1  = (const float*)d_in[1];
    const float* b1  = (const float*)d_in[2];
    const float* W2  = (const float*)d_in[3];
    const float* b2  = (const float*)d_in[4];
    const float* W3  = (const float*)d_in[5];
    const float* b3  = (const float*)d_in[6];
    const float* V1  = (const float*)d_in[7];
    const float* c1  = (const float*)d_in[8];
    const float* V2  = (const float*)d_in[9];
    const float* c2  = (const float*)d_in[10];
    const float* V3  = (const float*)d_in[11];
    const float* c3  = (const float*)d_in[12];

    prep_kernel<<<10, 512>>>(b1, b2, W3, b3, V1, c1, V2, c2, V3, c3);

    void* stage_ptr = nullptr;
    cudaGetSymbolAddress(&stage_ptr, g_stage);
    cudaMemcpyToSymbolAsync(cst, stage_ptr, N_CST * sizeof(u64), 0,
                            cudaMemcpyDeviceToDevice, 0);

    int B = in_sizes[0] / 385;
    int nhalf = B / 2;
    int blocks = (nhalf + 127) / 128;
    lila_kernel<<<blocks, 128>>>(inp, W1, W2, (float*)d_out, nhalf);
}

// round 7
// speedup vs baseline: 1.2631x; 1.1794x over previous
#include <cuda_runtime.h>

typedef unsigned long long u64;

__device__ __forceinline__ u64 pk2(float lo, float hi) {
    u64 r; asm("mov.b64 %0,{%1,%2};" : "=l"(r) : "f"(lo), "f"(hi)); return r;
}
__device__ __forceinline__ float2 up2(u64 v) {
    float2 f; asm("mov.b64 {%0,%1},%2;" : "=f"(f.x), "=f"(f.y) : "l"(v)); return f;
}
__device__ __forceinline__ u64 fma2(u64 a, u64 b, u64 c) {
    u64 d; asm("fma.rn.f32x2 %0,%1,%2,%3;" : "=l"(d) : "l"(a), "l"(b), "l"(c)); return d;
}
__device__ __forceinline__ u64 add2(u64 a, u64 b) {
    u64 d; asm("add.rn.f32x2 %0,%1,%2;" : "=l"(d) : "l"(a), "l"(b)); return d;
}
__device__ __forceinline__ u64 clamp2(u64 v) {
    float2 f = up2(v);
    f.x = fminf(fmaxf(f.x, -1.0f), 1.0f);
    f.y = fminf(fmaxf(f.y, -1.0f), 1.0f);
    return pk2(f.x, f.y);
}

// shared-memory u64 (duplicated-pair) layout — all offsets even (16B aligned)
#define O_W1 0        // 648  (54x12)
#define O_B1 648      // 12
#define O_W2 660      // 144  (12x12)
#define O_B2 804      // 12
#define O_W3 816      // 48   (12x4)
#define O_B3 864      // 4
#define O_V1 868      // 4640 (145x32)
#define O_C1 5508     // 32
#define O_C2 5540     // 32
#define O_V3 5572     // 32
#define O_C3 5604     // 1 (+1 pad)
#define N_U64 5606    // 44848 bytes

__global__ void __launch_bounds__(128, 3) lila_kernel(
    const float* __restrict__ inp,
    const float* __restrict__ W1, const float* __restrict__ b1,
    const float* __restrict__ W2, const float* __restrict__ b2,
    const float* __restrict__ W3, const float* __restrict__ b3,
    const float* __restrict__ V1, const float* __restrict__ c1,
    const float* __restrict__ V2, const float* __restrict__ c2,
    const float* __restrict__ V3, const float* __restrict__ c3,
    float* __restrict__ out, int nhalf)
{
    __shared__ __align__(16) u64 sw[N_U64];  // 44848 B
    __shared__ float sV2[1024];              // 4096 B -> total 48944 <= 48K

    for (int i = threadIdx.x; i < 648;  i += 128) { float v = W1[i]; sw[O_W1+i] = pk2(v,v); }
    for (int i = threadIdx.x; i < 12;   i += 128) { float v = b1[i]; sw[O_B1+i] = pk2(v,v);
                                                    float u = b2[i]; sw[O_B2+i] = pk2(u,u); }
    for (int i = threadIdx.x; i < 144;  i += 128) { float v = W2[i]; sw[O_W2+i] = pk2(v,v); }
    for (int i = threadIdx.x; i < 48;   i += 128) { float v = W3[i]; sw[O_W3+i] = pk2(v,v); }
    for (int i = threadIdx.x; i < 4;    i += 128) { float v = b3[i]; sw[O_B3+i] = pk2(v,v); }
    for (int i = threadIdx.x; i < 4640; i += 128) { float v = V1[i]; sw[O_V1+i] = pk2(v,v); }
    for (int i = threadIdx.x; i < 32;   i += 128) { float v = c1[i]; sw[O_C1+i] = pk2(v,v);
                                                    float u = c2[i]; sw[O_C2+i] = pk2(u,u);
                                                    float w = V3[i]; sw[O_V3+i] = pk2(w,w); }
    for (int i = threadIdx.x; i < 1024; i += 128) { sV2[i] = V2[i]; }
    if (threadIdx.x == 0) { float v = c3[0]; sw[O_C3] = pk2(v,v); }
    __syncthreads();

    int t = blockIdx.x * 128 + threadIdx.x;
    if (t >= nhalf) return;
    const float* p0 = inp + (size_t)(2 * t) * 385;   // 8B aligned
    const float* p1 = p0 + 385;                      // odd word offset

    u64 acc[32];
    #pragma unroll
    for (int j = 0; j < 32; j++) acc[j] = 0ull;

    // window pairs: (x, yy) and (x, yy+1), x in 0..5, yy in {0,2,4}
    #pragma unroll 1
    for (int wp = 0; wp < 18; wp++) {
        int x  = wp / 3;
        int yy = (wp - x * 3) * 2;
        int cbase = x * 48 + yy * 6;

        u64 ha[12], hb[12];
        #pragma unroll
        for (int n = 0; n < 12; n++) { ha[n] = sw[O_B1 + n]; hb[n] = ha[n]; }

        #pragma unroll 1
        for (int ox = 0; ox < 3; ox++) {
            const float*  r0 = p0 + cbase + ox * 48;
            const float*  r1 = p1 + cbase + ox * 48;
            const float2* q0 = reinterpret_cast<const float2*>(r0);
            const float2* q1 = reinterpret_cast<const float2*>(r1 - 1);
            const u64* wk = sw + O_W1 + ox * 216;

            u64 v[12];
            float carry;
            {
                float2 A0=__ldg(q0+0),A1=__ldg(q0+1),A2=__ldg(q0+2),
                       A3=__ldg(q0+3),A4=__ldg(q0+4),A5=__ldg(q0+5);
                float2 B0=__ldg(q1+0),B1=__ldg(q1+1),B2=__ldg(q1+2),B3=__ldg(q1+3),
                       B4=__ldg(q1+4),B5=__ldg(q1+5),B6=__ldg(q1+6);
                v[0]=pk2(A0.x,B0.y);  v[1]=pk2(A0.y,B1.x);
                v[2]=pk2(A1.x,B1.y);  v[3]=pk2(A1.y,B2.x);
                v[4]=pk2(A2.x,B2.y);  v[5]=pk2(A2.y,B3.x);
                v[6]=pk2(A3.x,B3.y);  v[7]=pk2(A3.y,B4.x);
                v[8]=pk2(A4.x,B4.y);  v[9]=pk2(A4.y,B5.x);
                v[10]=pk2(A5.x,B5.y); v[11]=pk2(A5.y,B6.x);
                carry = B6.y;
            }
            #pragma unroll
            for (int kk = 0; kk < 6; kk++) {
                u64 va = v[kk], vb = v[kk + 6];
                const ulonglong2* w2 = reinterpret_cast<const ulonglong2*>(wk + kk * 12);
                #pragma unroll
                for (int n2 = 0; n2 < 6; n2++) {
                    ulonglong2 w = w2[n2];
                    ha[2*n2]   = fma2(va, w.x, ha[2*n2]);
                    ha[2*n2+1] = fma2(va, w.y, ha[2*n2+1]);
                    hb[2*n2]   = fma2(vb, w.x, hb[2*n2]);
                    hb[2*n2+1] = fma2(vb, w.y, hb[2*n2+1]);
                }
            }
            {
                #pragma unroll
                for (int i = 0; i < 6; i++) v[i] = v[i + 6];
                float2 A6=__ldg(q0+6),A7=__ldg(q0+7),A8=__ldg(q0+8);
                float2 B7=__ldg(q1+7),B8=__ldg(q1+8),B9=__ldg(q1+9);
                v[6] =pk2(A6.x,carry); v[7] =pk2(A6.y,B7.x);
                v[8] =pk2(A7.x,B7.y);  v[9] =pk2(A7.y,B8.x);
                v[10]=pk2(A8.x,B8.y);  v[11]=pk2(A8.y,B9.x);
                carry = B9.y;
            }
            #pragma unroll
            for (int kk = 0; kk < 6; kk++) {
                u64 va = v[kk], vb = v[kk + 6];
                const ulonglong2* w2 = reinterpret_cast<const ulonglong2*>(wk + (6 + kk) * 12);
                #pragma unroll
                for (int n2 = 0; n2 < 6; n2++) {
                    ulonglong2 w = w2[n2];
                    ha[2*n2]   = fma2(va, w.x, ha[2*n2]);
                    ha[2*n2+1] = fma2(va, w.y, ha[2*n2+1]);
                    hb[2*n2]   = fma2(vb, w.x, hb[2*n2]);
                    hb[2*n2+1] = fma2(vb, w.y, hb[2*n2+1]);
                }
            }
            {
                #pragma unroll
                for (int i = 0; i < 6; i++) v[i] = v[i + 6];
                float2 A9=__ldg(q0+9),A10=__ldg(q0+10),A11=__ldg(q0+11);
                float2 B10=__ldg(q1+10),B11=__ldg(q1+11),B12=__ldg(q1+12);
                v[6] =pk2(A9.x,carry);  v[7] =pk2(A9.y,B10.x);
                v[8] =pk2(A10.x,B10.y); v[9] =pk2(A10.y,B11.x);
                v[10]=pk2(A11.x,B11.y); v[11]=pk2(A11.y,B12.x);
            }
            #pragma unroll
            for (int kk = 0; kk < 6; kk++) {
                u64 va = v[kk], vb = v[kk + 6];
                const ulonglong2* w2 = reinterpret_cast<const ulonglong2*>(wk + (12 + kk) * 12);
                #pragma unroll
                for (int n2 = 0; n2 < 6; n2++) {
                    ulonglong2 w = w2[n2];
                    ha[2*n2]   = fma2(va, w.x, ha[2*n2]);
                    ha[2*n2+1] = fma2(va, w.y, ha[2*n2+1]);
                    hb[2*n2]   = fma2(vb, w.x, hb[2*n2]);
                    hb[2*n2+1] = fma2(vb, w.y, hb[2*n2+1]);
                }
            }
        }
        #pragma unroll
        for (int n = 0; n < 12; n++) { ha[n] = clamp2(ha[n]); hb[n] = clamp2(hb[n]); }

        // layer 2: 12 -> 12 (LDS.128 weight pairs)
        u64 ga[12], gb[12];
        #pragma unroll
        for (int n = 0; n < 12; n++) { ga[n] = sw[O_B2 + n]; gb[n] = ga[n]; }
        #pragma unroll 4
        for (int k = 0; k < 12; k++) {
            const ulonglong2* w2 = reinterpret_cast<const ulonglong2*>(sw + O_W2 + k * 12);
            #pragma unroll
            for (int n2 = 0; n2 < 6; n2++) {
                ulonglong2 w = w2[n2];
                ga[2*n2]   = fma2(ha[k], w.x, ga[2*n2]);
                ga[2*n2+1] = fma2(ha[k], w.y, ga[2*n2+1]);
                gb[2*n2]   = fma2(hb[k], w.x, gb[2*n2]);
                gb[2*n2+1] = fma2(hb[k], w.y, gb[2*n2+1]);
            }
        }
        #pragma unroll
        for (int n = 0; n < 12; n++) { ga[n] = clamp2(ga[n]); gb[n] = clamp2(gb[n]); }

        // layer 3: 12 -> 4 (LDS.128 weight pairs)
        u64 sa[4], sb[4];
        #pragma unroll
        for (int q = 0; q < 4; q++) { sa[q] = sw[O_B3 + q]; sb[q] = sa[q]; }
        #pragma unroll
        for (int k = 0; k < 12; k++) {
            const ulonglong2* w2 = reinterpret_cast<const ulonglong2*>(sw + O_W3 + k * 4);
            #pragma unroll
            for (int q2 = 0; q2 < 2; q2++) {
                ulonglong2 w = w2[q2];
                sa[2*q2]   = fma2(ga[k], w.x, sa[2*q2]);
                sa[2*q2+1] = fma2(ga[k], w.y, sa[2*q2+1]);
                sb[2*q2]   = fma2(gb[k], w.x, sb[2*q2]);
                sb[2*q2+1] = fma2(gb[k], w.y, sb[2*q2+1]);
            }
        }
        #pragma unroll
        for (int q = 0; q < 4; q++) { sa[q] = clamp2(sa[q]); sb[q] = clamp2(sb[q]); }

        // fold sight into V1 accumulator (LDS.128 weight pairs)
        const u64* v1p = sw + O_V1 + (x * 6 + yy) * 4 * 32;
        #pragma unroll
        for (int q = 0; q < 4; q++) {
            const ulonglong2* wa2 = reinterpret_cast<const ulonglong2*>(v1p + q * 32);
            const ulonglong2* wb2 = reinterpret_cast<const ulonglong2*>(v1p + (4 + q) * 32);
            #pragma unroll
            for (int j2 = 0; j2 < 16; j2++) {
                ulonglong2 wa = wa2[j2];
                ulonglong2 wb = wb2[j2];
                acc[2*j2]   = fma2(sa[q], wa.x, acc[2*j2]);
                acc[2*j2+1] = fma2(sa[q], wa.y, acc[2*j2+1]);
                acc[2*j2]   = fma2(sb[q], wb.x, acc[2*j2]);
                acc[2*j2+1] = fma2(sb[q], wb.y, acc[2*j2+1]);
            }
        }
    }

    // finish V1 with inp[:,384], add c1, clamp -> e1
    u64 last = pk2(__ldg(p0 + 384), __ldg(p1 + 384));
    const u64* v1l = sw + O_V1 + 144 * 32;
    u64 e1[32];
    #pragma unroll
    for (int j = 0; j < 32; j++) {
        u64 v = fma2(last, v1l[j], acc[j]);
        e1[j] = clamp2(add2(v, sw[O_C1 + j]));
    }

    // V2 (32->32) + V3 (32->1) fused
    u64 o = sw[O_C3];
    #pragma unroll 1
    for (int j = 0; j < 32; j++) {
        u64 e = sw[O_C2 + j];
        #pragma unroll
        for (int k = 0; k < 32; k++) {
            float w = sV2[k * 32 + j];
            e = fma2(e1[k], pk2(w, w), e);
        }
        e = clamp2(e);
        o = fma2(e, sw[O_V3 + j], o);
    }
    o = clamp2(o);

    reinterpret_cast<float2*>(out)[t] = up2(o);
}

extern "C" void kernel_launch(void* const* d_in, const int* in_sizes, int n_in,
                              void* d_out, int out_size) {
    const float* inp = (const float*)d_in[0];
    const float* W1  = (const float*)d_in[1];
    const float* b1  = (const float*)d_in[2];
    const float* W2  = (const float*)d_in[3];
    const float* b2  = (const float*)d_in[4];
    const float* W3  = (const float*)d_in[5];
    const float* b3  = (const float*)d_in[6];
    const float* V1  = (const float*)d_in[7];
    const float* c1  = (const float*)d_in[8];
    const float* V2  = (const float*)d_in[9];
    const float* c2  = (const float*)d_in[10];
    const float* V3  = (const float*)d_in[11];
    const float* c3  = (const float*)d_in[12];

    int B = in_sizes[0] / 385;
    int nhalf = B / 2;
    int blocks = (nhalf + 127) / 128;

    lila_kernel<<<blocks, 128>>>(inp, W1, b1, W2, b2, W3, b3,
                                 V1, c1, V2, c2, V3, c3,
                                 (float*)d_out, nhalf);
}

// round 8
// speedup vs baseline: 1.5380x; 1.2176x over previous
#include <cuda_runtime.h>

typedef unsigned long long u64;

__device__ __forceinline__ u64 pk2(float lo, float hi) {
    u64 r; asm("mov.b64 %0,{%1,%2};" : "=l"(r) : "f"(lo), "f"(hi)); return r;
}
__device__ __forceinline__ float2 up2(u64 v) {
    float2 f; asm("mov.b64 {%0,%1},%2;" : "=f"(f.x), "=f"(f.y) : "l"(v)); return f;
}
__device__ __forceinline__ u64 fma2(u64 a, u64 b, u64 c) {
    u64 d; asm("fma.rn.f32x2 %0,%1,%2,%3;" : "=l"(d) : "l"(a), "l"(b), "l"(c)); return d;
}
__device__ __forceinline__ u64 add2(u64 a, u64 b) {
    u64 d; asm("add.rn.f32x2 %0,%1,%2;" : "=l"(d) : "l"(a), "l"(b)); return d;
}
__device__ __forceinline__ u64 clamp2(u64 v) {
    float2 f = up2(v);
    f.x = fminf(fmaxf(f.x, -1.0f), 1.0f);
    f.y = fminf(fmaxf(f.y, -1.0f), 1.0f);
    return pk2(f.x, f.y);
}

#define NPMAX 65536
// transposed, sample-pair-packed input: g_T[c][t] = {inp[2t][c], inp[2t+1][c]}
__device__ u64 g_T[385u * NPMAX];   // 201.85 MB scratch

// ------------------------- transpose + pack kernel -------------------------
// tiles of 64 samples x 32 cols; 256 threads
__global__ void transpose_kernel(const float* __restrict__ inp, int np)
{
    __shared__ float tile[64][33];
    int bx = blockIdx.x;            // col tile (0..12)
    int by = blockIdx.y;            // 64-sample tile
    int tid = threadIdx.x;
    int lx = tid & 31, ly = tid >> 5;
    int col = bx * 32 + lx;

    #pragma unroll
    for (int i = 0; i < 8; i++) {
        int r = ly + i * 8;
        float v = 0.0f;
        if (col < 385) v = inp[(size_t)(by * 64 + r) * 385 + col];
        tile[r][lx] = v;
    }
    __syncthreads();

    int pl = tid & 31;              // pair index within tile (0..31)
    int cl = tid >> 5;              // col-local base (0..7)
    #pragma unroll
    for (int i = 0; i < 4; i++) {
        int c  = cl + i * 8;
        int gc = bx * 32 + c;
        if (gc < 385) {
            u64 v = pk2(tile[2 * pl][c], tile[2 * pl + 1][c]);
            g_T[(size_t)gc * np + by * 32 + pl] = v;
        }
    }
}

// ------------------------------ main kernel -------------------------------
// shared-memory u64 (duplicated-pair) layout — all offsets even (16B aligned)
#define O_W1 0        // 648  (54x12)
#define O_B1 648      // 12
#define O_W2 660      // 144  (12x12)
#define O_B2 804      // 12
#define O_W3 816      // 48   (12x4)
#define O_B3 864      // 4
#define O_V1 868      // 4640 (145x32)
#define O_C1 5508     // 32
#define O_C2 5540     // 32
#define O_V3 5572     // 32
#define O_C3 5604     // 1 (+1 pad)
#define N_U64 5606    // 44848 bytes

__global__ void __launch_bounds__(128, 3) lila_kernel(
    const float* __restrict__ W1, const float* __restrict__ b1,
    const float* __restrict__ W2, const float* __restrict__ b2,
    const float* __restrict__ W3, const float* __restrict__ b3,
    const float* __restrict__ V1, const float* __restrict__ c1,
    const float* __restrict__ V2, const float* __restrict__ c2,
    const float* __restrict__ V3, const float* __restrict__ c3,
    float* __restrict__ out, int np)
{
    __shared__ __align__(16) u64 sw[N_U64];  // 44848 B
    __shared__ float sV2[1024];              // 4096 B

    for (int i = threadIdx.x; i < 648;  i += 128) { float v = W1[i]; sw[O_W1+i] = pk2(v,v); }
    for (int i = threadIdx.x; i < 12;   i += 128) { float v = b1[i]; sw[O_B1+i] = pk2(v,v);
                                                    float u = b2[i]; sw[O_B2+i] = pk2(u,u); }
    for (int i = threadIdx.x; i < 144;  i += 128) { float v = W2[i]; sw[O_W2+i] = pk2(v,v); }
    for (int i = threadIdx.x; i < 48;   i += 128) { float v = W3[i]; sw[O_W3+i] = pk2(v,v); }
    for (int i = threadIdx.x; i < 4;    i += 128) { float v = b3[i]; sw[O_B3+i] = pk2(v,v); }
    for (int i = threadIdx.x; i < 4640; i += 128) { float v = V1[i]; sw[O_V1+i] = pk2(v,v); }
    for (int i = threadIdx.x; i < 32;   i += 128) { float v = c1[i]; sw[O_C1+i] = pk2(v,v);
                                                    float u = c2[i]; sw[O_C2+i] = pk2(u,u);
                                                    float w = V3[i]; sw[O_V3+i] = pk2(w,w); }
    for (int i = threadIdx.x; i < 1024; i += 128) { sV2[i] = V2[i]; }
    if (threadIdx.x == 0) { float v = c3[0]; sw[O_C3] = pk2(v,v); }
    __syncthreads();

    int t = blockIdx.x * 128 + threadIdx.x;
    if (t >= np) return;

    u64 acc[32];
    #pragma unroll
    for (int j = 0; j < 32; j++) acc[j] = 0ull;

    // window pairs: (x, yy) and (x, yy+1), x in 0..5, yy in {0,2,4}
    #pragma unroll 1
    for (int wp = 0; wp < 18; wp++) {
        int x  = wp / 3;
        int yy = (wp - x * 3) * 2;
        int cbase = x * 48 + yy * 6;

        u64 ha[12], hb[12];
        #pragma unroll
        for (int n = 0; n < 12; n++) { ha[n] = sw[O_B1 + n]; hb[n] = ha[n]; }

        // layer 1: coalesced column loads from transposed packed input.
        // Window a uses local cols 0..17, window b uses 6..23 (rolling v[12]).
        #pragma unroll 1
        for (int ox = 0; ox < 3; ox++) {
            const u64* gcol = g_T + (size_t)(cbase + ox * 48) * np + t;
            const u64* wk = sw + O_W1 + ox * 216;

            u64 v[12];
            #pragma unroll
            for (int i = 0; i < 12; i++) v[i] = __ldg(gcol + (size_t)i * np);

            #pragma unroll
            for (int kk = 0; kk < 6; kk++) {
                u64 va = v[kk], vb = v[kk + 6];
                const ulonglong2* w2 = reinterpret_cast<const ulonglong2*>(wk + kk * 12);
                #pragma unroll
                for (int n2 = 0; n2 < 6; n2++) {
                    ulonglong2 w = w2[n2];
                    ha[2*n2]   = fma2(va, w.x, ha[2*n2]);
                    ha[2*n2+1] = fma2(va, w.y, ha[2*n2+1]);
                    hb[2*n2]   = fma2(vb, w.x, hb[2*n2]);
                    hb[2*n2+1] = fma2(vb, w.y, hb[2*n2+1]);
                }
            }
            #pragma unroll
            for (int i = 0; i < 6; i++) v[i] = v[i + 6];
            #pragma unroll
            for (int i = 0; i < 6; i++) v[6 + i] = __ldg(gcol + (size_t)(12 + i) * np);
            #pragma unroll
            for (int kk = 0; kk < 6; kk++) {
                u64 va = v[kk], vb = v[kk + 6];
                const ulonglong2* w2 = reinterpret_cast<const ulonglong2*>(wk + (6 + kk) * 12);
                #pragma unroll
                for (int n2 = 0; n2 < 6; n2++) {
                    ulonglong2 w = w2[n2];
                    ha[2*n2]   = fma2(va, w.x, ha[2*n2]);
                    ha[2*n2+1] = fma2(va, w.y, ha[2*n2+1]);
                    hb[2*n2]   = fma2(vb, w.x, hb[2*n2]);
                    hb[2*n2+1] = fma2(vb, w.y, hb[2*n2+1]);
                }
            }
            #pragma unroll
            for (int i = 0; i < 6; i++) v[i] = v[i + 6];
            #pragma unroll
            for (int i = 0; i < 6; i++) v[6 + i] = __ldg(gcol + (size_t)(18 + i) * np);
            #pragma unroll
            for (int kk = 0; kk < 6; kk++) {
                u64 va = v[kk], vb = v[kk + 6];
                const ulonglong2* w2 = reinterpret_cast<const ulonglong2*>(wk + (12 + kk) * 12);
                #pragma unroll
                for (int n2 = 0; n2 < 6; n2++) {
                    ulonglong2 w = w2[n2];
                    ha[2*n2]   = fma2(va, w.x, ha[2*n2]);
                    ha[2*n2+1] = fma2(va, w.y, ha[2*n2+1]);
                    hb[2*n2]   = fma2(vb, w.x, hb[2*n2]);
                    hb[2*n2+1] = fma2(vb, w.y, hb[2*n2+1]);
                }
            }
        }
        #pragma unroll
        for (int n = 0; n < 12; n++) { ha[n] = clamp2(ha[n]); hb[n] = clamp2(hb[n]); }

        // layer 2: 12 -> 12
        u64 ga[12], gb[12];
        #pragma unroll
        for (int n = 0; n < 12; n++) { ga[n] = sw[O_B2 + n]; gb[n] = ga[n]; }
        #pragma unroll 4
        for (int k = 0; k < 12; k++) {
            const ulonglong2* w2 = reinterpret_cast<const ulonglong2*>(sw + O_W2 + k * 12);
            #pragma unroll
            for (int n2 = 0; n2 < 6; n2++) {
                ulonglong2 w = w2[n2];
                ga[2*n2]   = fma2(ha[k], w.x, ga[2*n2]);
                ga[2*n2+1] = fma2(ha[k], w.y, ga[2*n2+1]);
                gb[2*n2]   = fma2(hb[k], w.x, gb[2*n2]);
                gb[2*n2+1] = fma2(hb[k], w.y, gb[2*n2+1]);
            }
        }
        #pragma unroll
        for (int n = 0; n < 12; n++) { ga[n] = clamp2(ga[n]); gb[n] = clamp2(gb[n]); }

        // layer 3: 12 -> 4
        u64 sa[4], sb[4];
        #pragma unroll
        for (int q = 0; q < 4; q++) { sa[q] = sw[O_B3 + q]; sb[q] = sa[q]; }
        #pragma unroll
        for (int k = 0; k < 12; k++) {
            const ulonglong2* w2 = reinterpret_cast<const ulonglong2*>(sw + O_W3 + k * 4);
            #pragma unroll
            for (int q2 = 0; q2 < 2; q2++) {
                ulonglong2 w = w2[q2];
                sa[2*q2]   = fma2(ga[k], w.x, sa[2*q2]);
                sa[2*q2+1] = fma2(ga[k], w.y, sa[2*q2+1]);
                sb[2*q2]   = fma2(gb[k], w.x, sb[2*q2]);
                sb[2*q2+1] = fma2(gb[k], w.y, sb[2*q2+1]);
            }
        }
        #pragma unroll
        for (int q = 0; q < 4; q++) { sa[q] = clamp2(sa[q]); sb[q] = clamp2(sb[q]); }

        // fold sight into V1 accumulator
        const u64* v1p = sw + O_V1 + (x * 6 + yy) * 4 * 32;
        #pragma unroll
        for (int q = 0; q < 4; q++) {
            const ulonglong2* wa2 = reinterpret_cast<const ulonglong2*>(v1p + q * 32);
            const ulonglong2* wb2 = reinterpret_cast<const ulonglong2*>(v1p + (4 + q) * 32);
            #pragma unroll
            for (int j2 = 0; j2 < 16; j2++) {
                ulonglong2 wa = wa2[j2];
                ulonglong2 wb = wb2[j2];
                acc[2*j2]   = fma2(sa[q], wa.x, acc[2*j2]);
                acc[2*j2+1] = fma2(sa[q], wa.y, acc[2*j2+1]);
                acc[2*j2]   = fma2(sb[q], wb.x, acc[2*j2]);
                acc[2*j2+1] = fma2(sb[q], wb.y, acc[2*j2+1]);
            }
        }
    }

    // finish V1 with inp[:,384], add c1, clamp -> e1
    u64 last = __ldg(g_T + (size_t)384 * np + t);
    const u64* v1l = sw + O_V1 + 144 * 32;
    u64 e1[32];
    #pragma unroll
    for (int j = 0; j < 32; j++) {
        u64 v = fma2(last, v1l[j], acc[j]);
        e1[j] = clamp2(add2(v, sw[O_C1 + j]));
    }

    // V2 (32->32) + V3 (32->1) fused
    u64 o = sw[O_C3];
    #pragma unroll 1
    for (int j = 0; j < 32; j++) {
        u64 e = sw[O_C2 + j];
        #pragma unroll
        for (int k = 0; k < 32; k++) {
            float w = sV2[k * 32 + j];
            e = fma2(e1[k], pk2(w, w), e);
        }
        e = clamp2(e);
        o = fma2(e, sw[O_V3 + j], o);
    }
    o = clamp2(o);

    reinterpret_cast<float2*>(out)[t] = up2(o);
}

extern "C" void kernel_launch(void* const* d_in, const int* in_sizes, int n_in,
                              void* d_out, int out_size) {
    const float* inp = (const float*)d_in[0];
    const float* W1  = (const float*)d_in[1];
    const float* b1  = (const float*)d_in[2];
    const float* W2  = (const float*)d_in[3];
    const float* b2  = (const float*)d_in[4];
    const float* W3  = (const float*)d_in[5];
    const float* b3  = (const float*)d_in[6];
    const float* V1  = (const float*)d_in[7];
    const float* c1  = (const float*)d_in[8];
    const float* V2  = (const float*)d_in[9];
    const float* c2  = (const float*)d_in[10];
    const float* V3  = (const float*)d_in[11];
    const float* c3  = (const float*)d_in[12];

    int B  = in_sizes[0] / 385;   // 131072
    int np = B / 2;               // 65536 sample-pairs

    // 1) transpose + pack: inp [B,385] -> g_T [385][np] u64
    dim3 tgrid(13, B / 64);
    transpose_kernel<<<tgrid, 256>>>(inp, np);

    // 2) main fused MLP
    int blocks = (np + 127) / 128;
    lila_kernel<<<blocks, 128>>>(W1, b1, W2, b2, W3, b3,
                                 V1, c1, V2, c2, V3, c3,
                                 (float*)d_out, np);
}